// round 1
// baseline (speedup 1.0000x reference)
#include <cuda_runtime.h>
#include <cstdint>
#include <cstddef>

// ---------------------------------------------------------------------------
// Problem constants
// ---------------------------------------------------------------------------
#define Bsz 8
#define Lsz 1024
#define Hsz 1024
#define Msz 128
#define Vsz 32
#define VV  (Vsz * Vsz)          // 1024
#define LN_EPS 1e-5f

// Output layout: concat of flattened outputs (promoted to float32)
//   logits      (B*M*M, VV)      = 134,217,728
//   mlm_logits  (B, L, V)        =     262,144
//   diag_mask   (B*M*M,)         =     131,072
//   mask_aa     (B, L, 1)        =       8,192
//   pair_mask   (B, L, L, 1)     =   8,388,608
static const size_t OFF_LOGITS = 0;
static const size_t OFF_MLM    = 134217728;
static const size_t OFF_DIAG   = OFF_MLM + (size_t)Bsz * Lsz * Vsz;          // 134479872
static const size_t OFF_MASKAA = OFF_DIAG + (size_t)Bsz * Msz * Msz;         // 134610944
static const size_t OFF_PAIR   = OFF_MASKAA + (size_t)Bsz * Lsz;             // 134619136

// ---------------------------------------------------------------------------
// Device scratch (static; no allocations allowed)
// ---------------------------------------------------------------------------
__device__ float g_xnorm[(size_t)Bsz * Lsz * Hsz];   // 32 MB  layernormed x
__device__ float g_xm[(size_t)Bsz * Msz * Hsz];      // 4 MB   gathered masked_x
__device__ float g_q [(size_t)Bsz * Msz * Hsz];      // 4 MB
__device__ float g_k [(size_t)Bsz * Msz * Hsz];      // 4 MB
__device__ int   g_span[Bsz * Lsz];

// ---------------------------------------------------------------------------
// Kernel 1: LayerNorm (one block per row) + fused MLM logits (V=32)
// ---------------------------------------------------------------------------
__global__ __launch_bounds__(256) void ln_mlm_kernel(
    const float* __restrict__ x, const float* __restrict__ gamma,
    const float* __restrict__ beta, const float* __restrict__ wmlm,
    float* __restrict__ out)
{
    const int row = blockIdx.x;          // 0 .. B*L-1
    const int t   = threadIdx.x;         // 256 threads
    __shared__ float sx[Hsz];
    __shared__ float red[16];
    __shared__ float s_mu, s_rs;

    const float4* xr = (const float4*)(x + (size_t)row * Hsz);
    float4 v = xr[t];
    float s  = v.x + v.y + v.z + v.w;
    float ss = v.x*v.x + v.y*v.y + v.z*v.z + v.w*v.w;
    #pragma unroll
    for (int o = 16; o; o >>= 1) {
        s  += __shfl_xor_sync(0xffffffffu, s,  o);
        ss += __shfl_xor_sync(0xffffffffu, ss, o);
    }
    if ((t & 31) == 0) { red[t >> 5] = s; red[8 + (t >> 5)] = ss; }
    __syncthreads();
    if (t == 0) {
        float a = 0.f, b2 = 0.f;
        #pragma unroll
        for (int i = 0; i < 8; i++) { a += red[i]; b2 += red[8 + i]; }
        float mu  = a * (1.0f / Hsz);
        float var = b2 * (1.0f / Hsz) - mu * mu;
        s_mu = mu;
        s_rs = rsqrtf(var + LN_EPS);
    }
    __syncthreads();
    const float mu = s_mu, rs = s_rs;
    float4 g4 = ((const float4*)gamma)[t];
    float4 b4 = ((const float4*)beta)[t];
    float4 n;
    n.x = (v.x - mu) * rs * g4.x + b4.x;
    n.y = (v.y - mu) * rs * g4.y + b4.y;
    n.z = (v.z - mu) * rs * g4.z + b4.z;
    n.w = (v.w - mu) * rs * g4.w + b4.w;
    ((float4*)(g_xnorm + (size_t)row * Hsz))[t] = n;
    ((float4*)sx)[t] = n;
    __syncthreads();

    // MLM: warp w computes v = w*4 .. w*4+3
    const int w = t >> 5, lane = t & 31;
    float p0 = 0.f, p1 = 0.f, p2 = 0.f, p3 = 0.f;
    const float* w0 = wmlm + (size_t)(w * 4 + 0) * Hsz;
    const float* w1 = wmlm + (size_t)(w * 4 + 1) * Hsz;
    const float* w2 = wmlm + (size_t)(w * 4 + 2) * Hsz;
    const float* w3 = wmlm + (size_t)(w * 4 + 3) * Hsz;
    for (int h = lane; h < Hsz; h += 32) {
        float xv = sx[h];
        p0 = fmaf(xv, __ldg(w0 + h), p0);
        p1 = fmaf(xv, __ldg(w1 + h), p1);
        p2 = fmaf(xv, __ldg(w2 + h), p2);
        p3 = fmaf(xv, __ldg(w3 + h), p3);
    }
    #pragma unroll
    for (int o = 16; o; o >>= 1) {
        p0 += __shfl_xor_sync(0xffffffffu, p0, o);
        p1 += __shfl_xor_sync(0xffffffffu, p1, o);
        p2 += __shfl_xor_sync(0xffffffffu, p2, o);
        p3 += __shfl_xor_sync(0xffffffffu, p3, o);
    }
    if (lane == 0) {
        float* dst = out + OFF_MLM + (size_t)row * Vsz + w * 4;
        dst[0] = p0; dst[1] = p1; dst[2] = p2; dst[3] = p3;
    }
}

// ---------------------------------------------------------------------------
// Kernel 2: gather masked rows  xm[b*M+m] = xnorm[b*L + mask_idx[b,m]]
// ---------------------------------------------------------------------------
__global__ __launch_bounds__(256) void gather_kernel(const int* __restrict__ mask_idx)
{
    const int g = blockIdx.x;            // 0 .. B*M-1
    const int b = g >> 7;
    const int src = mask_idx[g];
    const float4* s = (const float4*)(g_xnorm + ((size_t)(b * Lsz + src)) * Hsz);
    float4* d = (float4*)(g_xm + (size_t)g * Hsz);
    d[threadIdx.x] = s[threadIdx.x];
}

// ---------------------------------------------------------------------------
// SGEMM body: C[128,128] tile, TN layout (both operands K-contiguous), K=1024
// 256 threads, 8x8 micro-tile per thread (split 4+4).
// ---------------------------------------------------------------------------
template <bool SCALE>
__device__ __forceinline__ void sgemm_body_128(
    const float* __restrict__ A,   // 128 rows x 1024, k-contiguous (rows of C)
    const float* __restrict__ Bm,  // 128 rows x 1024, k-contiguous (cols of C)
    const float* __restrict__ qs,  // shared, 1024 floats (only if SCALE)
    float* __restrict__ C, int ldc)
{
    __shared__ float As[8][128];
    __shared__ float Bs[8][128];
    const int tid = threadIdx.x;
    const int tx = tid & 15, ty = tid >> 4;
    const int lr = tid >> 1;             // 0..127
    const int lk = (tid & 1) * 4;        // 0 or 4

    float acc[8][8];
    #pragma unroll
    for (int r = 0; r < 8; r++)
        #pragma unroll
        for (int c = 0; c < 8; c++) acc[r][c] = 0.f;

    for (int k0 = 0; k0 < Hsz; k0 += 8) {
        float4 av = *(const float4*)(A + (size_t)lr * Hsz + k0 + lk);
        float4 bv = *(const float4*)(Bm + (size_t)lr * Hsz + k0 + lk);
        if (SCALE) {
            av.x *= qs[k0 + lk + 0];
            av.y *= qs[k0 + lk + 1];
            av.z *= qs[k0 + lk + 2];
            av.w *= qs[k0 + lk + 3];
        }
        As[lk + 0][lr] = av.x; As[lk + 1][lr] = av.y;
        As[lk + 2][lr] = av.z; As[lk + 3][lr] = av.w;
        Bs[lk + 0][lr] = bv.x; Bs[lk + 1][lr] = bv.y;
        Bs[lk + 2][lr] = bv.z; Bs[lk + 3][lr] = bv.w;
        __syncthreads();
        #pragma unroll
        for (int kk = 0; kk < 8; kk++) {
            float a[8], bb[8];
            *(float4*)(a)      = *(const float4*)&As[kk][ty * 4];
            *(float4*)(a + 4)  = *(const float4*)&As[kk][64 + ty * 4];
            *(float4*)(bb)     = *(const float4*)&Bs[kk][tx * 4];
            *(float4*)(bb + 4) = *(const float4*)&Bs[kk][64 + tx * 4];
            #pragma unroll
            for (int r = 0; r < 8; r++)
                #pragma unroll
                for (int c = 0; c < 8; c++)
                    acc[r][c] = fmaf(a[r], bb[c], acc[r][c]);
        }
        __syncthreads();
    }

    #pragma unroll
    for (int r = 0; r < 8; r++) {
        const int row = (r < 4) ? (ty * 4 + r) : (64 + ty * 4 + (r - 4));
        float4 o0 = make_float4(acc[r][0], acc[r][1], acc[r][2], acc[r][3]);
        float4 o1 = make_float4(acc[r][4], acc[r][5], acc[r][6], acc[r][7]);
        *(float4*)(C + (size_t)row * ldc + tx * 4)      = o0;
        *(float4*)(C + (size_t)row * ldc + 64 + tx * 4) = o1;
    }
}

// ---------------------------------------------------------------------------
// Kernel 3: q/k projections. grid (8 o-tiles, 8 m-tiles, 2)
// ---------------------------------------------------------------------------
__global__ __launch_bounds__(256, 2) void qk_gemm_kernel(
    const float* __restrict__ Wq, const float* __restrict__ Wk)
{
    const float* Bmat = blockIdx.z ? Wk : Wq;
    float* Cbase      = blockIdx.z ? g_k : g_q;
    const int rowBase = blockIdx.y * 128;
    const int colBase = blockIdx.x * 128;
    const float* A = g_xm + (size_t)rowBase * Hsz;
    const float* B = Bmat + (size_t)colBase * Hsz;
    float* C = Cbase + (size_t)rowBase * Hsz + colBase;
    sgemm_body_128<false>(A, B, nullptr, C, Hsz);
}

// ---------------------------------------------------------------------------
// Kernel 4: main batched contraction.
// block (vt, bi): C[j, v] = sum_h (k[b,j,h]*q[b,i,h]) * W_embed[vt*128+v, h]
// ---------------------------------------------------------------------------
__global__ __launch_bounds__(256, 2) void logits_gemm_kernel(
    const float* __restrict__ Wembed, float* __restrict__ out)
{
    const int vt = blockIdx.x;           // 0..7
    const int bi = blockIdx.y;           // 0..1023 (b*M + i)
    const int b  = bi >> 7;

    __shared__ float qs[Hsz];
    {
        const float4* qr = (const float4*)(g_q + (size_t)bi * Hsz);
        ((float4*)qs)[threadIdx.x] = qr[threadIdx.x];
    }
    __syncthreads();

    const float* A = g_k + (size_t)b * (Msz * Hsz);
    const float* B = Wembed + (size_t)vt * 128 * Hsz;
    float* C = out + OFF_LOGITS + (size_t)bi * (Msz * VV) + (size_t)vt * 128;
    sgemm_body_128<true>(A, B, qs, C, VV);
}

// ---------------------------------------------------------------------------
// Mask kernels
// ---------------------------------------------------------------------------
__global__ void span_kernel(const int* __restrict__ mask_idx, float* __restrict__ out)
{
    const int b = blockIdx.x;
    const int t = threadIdx.x;           // 1024 threads = L
    __shared__ int mi[Msz];
    if (t < Msz) mi[t] = mask_idx[b * Msz + t];
    __syncthreads();
    int in = 0;
    #pragma unroll 8
    for (int m = 0; m < Msz; m++) in |= (mi[m] == t);
    g_span[b * Lsz + t] = in;
    out[OFF_MASKAA + (size_t)b * Lsz + t] = (float)in;
}

__global__ void diag_kernel(float* __restrict__ out)
{
    const int t = blockIdx.x * 256 + threadIdx.x;     // 0 .. 131071
    const int r = t & (Msz * Msz - 1);
    const int i = r >> 7, j = r & 127;
    out[OFF_DIAG + t] = (i == j) ? 1.0f : 0.0f;
}

__global__ void pair_kernel(float* __restrict__ out)
{
    const int idx = blockIdx.x * 256 + threadIdx.x;   // float4 index, 2,097,152 total
    const int b   = idx >> 18;                        // 262144 groups per batch
    const int rem = idx & 262143;
    const int l1  = rem >> 8;                         // 256 groups per row
    const int l2g = (rem & 255) * 4;
    const float s1 = (float)g_span[b * Lsz + l1];
    const int* sp = g_span + b * Lsz + l2g;
    float4 o;
    o.x = s1 * sp[0]; o.y = s1 * sp[1]; o.z = s1 * sp[2]; o.w = s1 * sp[3];
    ((float4*)(out + OFF_PAIR))[idx] = o;
}

// ---------------------------------------------------------------------------
// Launch
// ---------------------------------------------------------------------------
extern "C" void kernel_launch(void* const* d_in, const int* in_sizes, int n_in,
                              void* d_out, int out_size)
{
    const float* x_enc    = (const float*)d_in[0];
    const float* ln_gamma = (const float*)d_in[1];
    const float* ln_beta  = (const float*)d_in[2];
    const float* Wq       = (const float*)d_in[3];
    const float* Wk       = (const float*)d_in[4];
    const float* W_embed  = (const float*)d_in[5];
    const float* W_mlm    = (const float*)d_in[6];
    const int*   mask_idx = (const int*)d_in[7];
    float* out = (float*)d_out;

    ln_mlm_kernel<<<Bsz * Lsz, 256>>>(x_enc, ln_gamma, ln_beta, W_mlm, out);
    gather_kernel<<<Bsz * Msz, 256>>>(mask_idx);
    qk_gemm_kernel<<<dim3(8, 8, 2), 256>>>(Wq, Wk);
    logits_gemm_kernel<<<dim3(8, Bsz * Msz), 256>>>(W_embed, out);
    span_kernel<<<Bsz, Lsz>>>(mask_idx, out);
    diag_kernel<<<(Bsz * Msz * Msz) / 256, 256>>>(out);
    pair_kernel<<<(Bsz * Lsz * Lsz / 4) / 256, 256>>>(out);
}

// round 7
// speedup vs baseline: 2.2038x; 2.2038x over previous
#include <cuda_runtime.h>
#include <cuda_bf16.h>
#include <cstdint>
#include <cstddef>

// ---------------------------------------------------------------------------
// Problem constants
// ---------------------------------------------------------------------------
#define Bsz 8
#define Lsz 1024
#define Hsz 1024
#define Msz 128
#define Vsz 32
#define VV  (Vsz * Vsz)          // 1024
#define LN_EPS 1e-5f
#define NCHUNK 32                // K chunks of 32

// Output layout offsets (floats)
static const size_t OFF_LOGITS = 0;
static const size_t OFF_MLM    = 134217728;
static const size_t OFF_DIAG   = OFF_MLM + (size_t)Bsz * Lsz * Vsz;
static const size_t OFF_MASKAA = OFF_DIAG + (size_t)Bsz * Msz * Msz;
static const size_t OFF_PAIR   = OFF_MASKAA + (size_t)Bsz * Lsz;

// ---------------------------------------------------------------------------
// Device scratch
// ---------------------------------------------------------------------------
__device__ float g_xnorm[(size_t)Bsz * Lsz * Hsz];   // 32 MB
__device__ float g_xm[(size_t)Bsz * Msz * Hsz];      // 4 MB
__device__ float g_q [(size_t)Bsz * Msz * Hsz];      // 4 MB
__device__ float g_k [(size_t)Bsz * Msz * Hsz];      // 4 MB
__device__ int   g_span[Bsz * Lsz];
// W_embed split hi/lo bf16, stored in mma-fragment layout per (ntile, chunk):
// [nt(8)][chunk(32)] x 16KB tile  = [hi 8KB | lo 8KB]
// within hi/lo: addr = (((s*16 + nf)*32) + lane)*8 + breg*4
__device__ __align__(1024) uint8_t g_Wt[8 * NCHUNK * 16384];   // 4 MB

// ---------------------------------------------------------------------------
// Helpers
// ---------------------------------------------------------------------------
__device__ __forceinline__ uint32_t smem_u32(const void* p) {
    uint32_t a;
    asm("{ .reg .u64 t; cvta.to.shared.u64 t, %1; cvt.u32.u64 %0, t; }"
        : "=r"(a) : "l"(p));
    return a;
}

// pack two fp32 into bf16x2 (lo elem in low 16 bits)
__device__ __forceinline__ uint32_t pack_bf16(float lo, float hi) {
    uint32_t r;
    asm("cvt.rn.bf16x2.f32 %0, %1, %2;" : "=r"(r) : "f"(hi), "f"(lo));
    return r;
}
// split pair (x0,x1) into hi bf16x2 + residual-lo bf16x2
__device__ __forceinline__ void split2(float x0, float x1, uint32_t& h, uint32_t& l) {
    h = pack_bf16(x0, x1);
    float h0 = __uint_as_float(h << 16);
    float h1 = __uint_as_float(h & 0xFFFF0000u);
    l = pack_bf16(x0 - h0, x1 - h1);
}

#define CP_ASYNC16(dst_u32, src_ptr) \
    asm volatile("cp.async.cg.shared.global [%0], [%1], 16;" \
                 :: "r"(dst_u32), "l"(src_ptr) : "memory")
#define CP_COMMIT()  asm volatile("cp.async.commit_group;" ::: "memory")
#define CP_WAIT0()   asm volatile("cp.async.wait_group 0;" ::: "memory")

#define MMA_BF16(c, a, bb) \
    asm volatile("mma.sync.aligned.m16n8k16.row.col.f32.bf16.bf16.f32 " \
                 "{%0,%1,%2,%3},{%4,%5,%6,%7},{%8,%9},{%0,%1,%2,%3};" \
                 : "+f"((c)[0]), "+f"((c)[1]), "+f"((c)[2]), "+f"((c)[3]) \
                 : "r"((a)[0]), "r"((a)[1]), "r"((a)[2]), "r"((a)[3]), \
                   "r"((bb)[0]), "r"((bb)[1]))

// ---------------------------------------------------------------------------
// Kernel 0: split W_embed into bf16 hi/lo in mma B-fragment layout.
// grid (32 chunks, 8 ntiles) x 256 threads.
// B frag (m16n8k16): breg b0: k=(lane%4)*2+{0,1}, n=lane/4 ; b1: k+8.
// ---------------------------------------------------------------------------
__global__ __launch_bounds__(256) void wsplit_kernel(const float* __restrict__ W)
{
    const int ch = blockIdx.x, nt = blockIdx.y, tid = threadIdx.x;
    const int v  = tid >> 1;              // 0..127 (n within tile)
    const int sh = tid & 1;               // k16 step within chunk32
    const int hbase = ch * 32 + sh * 16;
    const float4* src = (const float4*)(W + (size_t)(nt * 128 + v) * Hsz + hbase);
    uint8_t* tile = g_Wt + (size_t)(nt * NCHUNK + ch) * 16384;
    const int nf = v >> 3;
    const int lbase = (v & 7) * 4;
    #pragma unroll
    for (int g = 0; g < 4; g++) {
        float4 x = src[g];
        #pragma unroll
        for (int e = 0; e < 2; e++) {
            const int pl = g * 2 + e;     // k-pair 0..7 within k16
            uint32_t h, l;
            if (e == 0) split2(x.x, x.y, h, l);
            else        split2(x.z, x.w, h, l);
            const uint32_t off =
                (uint32_t)(((sh * 16 + nf) * 32 + lbase + (pl & 3)) * 8 + (pl >> 2) * 4);
            *(uint32_t*)(tile + off)        = h;
            *(uint32_t*)(tile + 8192 + off) = l;
        }
    }
}

// ---------------------------------------------------------------------------
// Kernel 1: LayerNorm + fused MLM logits
// ---------------------------------------------------------------------------
__global__ __launch_bounds__(256) void ln_mlm_kernel(
    const float* __restrict__ x, const float* __restrict__ gamma,
    const float* __restrict__ beta, const float* __restrict__ wmlm,
    float* __restrict__ out)
{
    const int row = blockIdx.x;
    const int t   = threadIdx.x;
    __shared__ float sx[Hsz];
    __shared__ float red[16];
    __shared__ float s_mu, s_rs;

    const float4* xr = (const float4*)(x + (size_t)row * Hsz);
    float4 v = xr[t];
    float s  = v.x + v.y + v.z + v.w;
    float ss = v.x*v.x + v.y*v.y + v.z*v.z + v.w*v.w;
    #pragma unroll
    for (int o = 16; o; o >>= 1) {
        s  += __shfl_xor_sync(0xffffffffu, s,  o);
        ss += __shfl_xor_sync(0xffffffffu, ss, o);
    }
    if ((t & 31) == 0) { red[t >> 5] = s; red[8 + (t >> 5)] = ss; }
    __syncthreads();
    if (t == 0) {
        float a = 0.f, b2 = 0.f;
        #pragma unroll
        for (int i = 0; i < 8; i++) { a += red[i]; b2 += red[8 + i]; }
        float mu  = a * (1.0f / Hsz);
        float var = b2 * (1.0f / Hsz) - mu * mu;
        s_mu = mu;
        s_rs = rsqrtf(var + LN_EPS);
    }
    __syncthreads();
    const float mu = s_mu, rs = s_rs;
    float4 g4 = ((const float4*)gamma)[t];
    float4 b4 = ((const float4*)beta)[t];
    float4 n;
    n.x = (v.x - mu) * rs * g4.x + b4.x;
    n.y = (v.y - mu) * rs * g4.y + b4.y;
    n.z = (v.z - mu) * rs * g4.z + b4.z;
    n.w = (v.w - mu) * rs * g4.w + b4.w;
    ((float4*)(g_xnorm + (size_t)row * Hsz))[t] = n;
    ((float4*)sx)[t] = n;
    __syncthreads();

    const int w = t >> 5, lane = t & 31;
    float p0 = 0.f, p1 = 0.f, p2 = 0.f, p3 = 0.f;
    const float* w0 = wmlm + (size_t)(w * 4 + 0) * Hsz;
    const float* w1 = wmlm + (size_t)(w * 4 + 1) * Hsz;
    const float* w2 = wmlm + (size_t)(w * 4 + 2) * Hsz;
    const float* w3 = wmlm + (size_t)(w * 4 + 3) * Hsz;
    for (int h = lane; h < Hsz; h += 32) {
        float xv = sx[h];
        p0 = fmaf(xv, __ldg(w0 + h), p0);
        p1 = fmaf(xv, __ldg(w1 + h), p1);
        p2 = fmaf(xv, __ldg(w2 + h), p2);
        p3 = fmaf(xv, __ldg(w3 + h), p3);
    }
    #pragma unroll
    for (int o = 16; o; o >>= 1) {
        p0 += __shfl_xor_sync(0xffffffffu, p0, o);
        p1 += __shfl_xor_sync(0xffffffffu, p1, o);
        p2 += __shfl_xor_sync(0xffffffffu, p2, o);
        p3 += __shfl_xor_sync(0xffffffffu, p3, o);
    }
    if (lane == 0) {
        float* dst = out + OFF_MLM + (size_t)row * Vsz + w * 4;
        dst[0] = p0; dst[1] = p1; dst[2] = p2; dst[3] = p3;
    }
}

// ---------------------------------------------------------------------------
// Kernel 2: gather masked rows
// ---------------------------------------------------------------------------
__global__ __launch_bounds__(256) void gather_kernel(const int* __restrict__ mask_idx)
{
    const int g = blockIdx.x;
    const int b = g >> 7;
    const int src = mask_idx[g];
    const float4* s = (const float4*)(g_xnorm + ((size_t)(b * Lsz + src)) * Hsz);
    float4* d = (float4*)(g_xm + (size_t)g * Hsz);
    d[threadIdx.x] = s[threadIdx.x];
}

// ---------------------------------------------------------------------------
// fp32 SGEMM body (q/k projections)
// ---------------------------------------------------------------------------
__device__ __forceinline__ void sgemm_body_128(
    const float* __restrict__ A, const float* __restrict__ Bm,
    float* __restrict__ C, int ldc)
{
    __shared__ float As[8][128];
    __shared__ float Bs[8][128];
    const int tid = threadIdx.x;
    const int tx = tid & 15, ty = tid >> 4;
    const int lr = tid >> 1;
    const int lk = (tid & 1) * 4;

    float acc[8][8];
    #pragma unroll
    for (int r = 0; r < 8; r++)
        #pragma unroll
        for (int c = 0; c < 8; c++) acc[r][c] = 0.f;

    for (int k0 = 0; k0 < Hsz; k0 += 8) {
        float4 av = *(const float4*)(A + (size_t)lr * Hsz + k0 + lk);
        float4 bv = *(const float4*)(Bm + (size_t)lr * Hsz + k0 + lk);
        As[lk + 0][lr] = av.x; As[lk + 1][lr] = av.y;
        As[lk + 2][lr] = av.z; As[lk + 3][lr] = av.w;
        Bs[lk + 0][lr] = bv.x; Bs[lk + 1][lr] = bv.y;
        Bs[lk + 2][lr] = bv.z; Bs[lk + 3][lr] = bv.w;
        __syncthreads();
        #pragma unroll
        for (int kk = 0; kk < 8; kk++) {
            float a[8], bb[8];
            *(float4*)(a)      = *(const float4*)&As[kk][ty * 4];
            *(float4*)(a + 4)  = *(const float4*)&As[kk][64 + ty * 4];
            *(float4*)(bb)     = *(const float4*)&Bs[kk][tx * 4];
            *(float4*)(bb + 4) = *(const float4*)&Bs[kk][64 + tx * 4];
            #pragma unroll
            for (int r = 0; r < 8; r++)
                #pragma unroll
                for (int c = 0; c < 8; c++)
                    acc[r][c] = fmaf(a[r], bb[c], acc[r][c]);
        }
        __syncthreads();
    }
    #pragma unroll
    for (int r = 0; r < 8; r++) {
        const int row = (r < 4) ? (ty * 4 + r) : (64 + ty * 4 + (r - 4));
        *(float4*)(C + (size_t)row * ldc + tx * 4)      = make_float4(acc[r][0], acc[r][1], acc[r][2], acc[r][3]);
        *(float4*)(C + (size_t)row * ldc + 64 + tx * 4) = make_float4(acc[r][4], acc[r][5], acc[r][6], acc[r][7]);
    }
}

__global__ __launch_bounds__(256, 2) void qk_gemm_kernel(
    const float* __restrict__ Wq, const float* __restrict__ Wk)
{
    const float* Bmat = blockIdx.z ? Wk : Wq;
    float* Cbase      = blockIdx.z ? g_k : g_q;
    const int rowBase = blockIdx.y * 128;
    const int colBase = blockIdx.x * 128;
    sgemm_body_128(g_xm + (size_t)rowBase * Hsz, Bmat + (size_t)colBase * Hsz,
                   Cbase + (size_t)rowBase * Hsz + colBase, Hsz);
}

// ---------------------------------------------------------------------------
// Kernel 4: logits contraction via mma.sync bf16 split 3-pass.
// grid (8 vtiles, 1024 bi), 256 threads, 2 CTA/SM.
// CTA: C[j=128, v=128] += sum_h (k[b,j,h]*q[bi,h]) * W[v,h], K=1024, 32 chunks of 32.
// smem stage (32KB): [A_hi 8K][A_lo 8K][W_hi 8K][W_lo 8K], double buffered.
// A frag layout: addr = ((s*8 + mtile)*32 + lane)*16 + areg*4
// W frag layout: addr = ((s*16 + nf)*32 + lane)*8 + breg*4
// ---------------------------------------------------------------------------
#define STAGE_SZ 32768
#define SMEM_MMA (2 * STAGE_SZ)

__global__ __launch_bounds__(256, 2) void logits_mma_kernel(float* __restrict__ out)
{
    extern __shared__ char sm[];
    const int tid = threadIdx.x;
    const int nt  = blockIdx.x;          // v-tile 0..7
    const int bi  = blockIdx.y;          // 0..1023 == b*128 + i
    const int b   = bi >> 7;
    const int w    = tid >> 5, lane = tid & 31;
    const int mh   = w & 1;              // m-half (0: j 0-63, 1: j 64-127)
    const int nq   = w >> 1;             // n-quarter (32 cols)

    // producer indexing: thread -> (row r, k16-step sh)
    const int r  = tid >> 1;
    const int sh = tid & 1;
    const int mt_p   = r >> 4;
    const int rl     = r & 15;
    const int reg_hi = (rl >> 3) & 1;    // +1 if row in upper 8 of m16
    const int lane_p = (rl & 7) * 4;

    const float4* kp = (const float4*)(g_k + (size_t)(b * Msz + r) * Hsz + sh * 16);
    const float4* qp = (const float4*)(g_q + (size_t)bi * Hsz + sh * 16);
    const uint8_t* wtiles = g_Wt + (size_t)nt * NCHUNK * 16384;

    float acc[4][4][4];
    #pragma unroll
    for (int a = 0; a < 4; a++)
        #pragma unroll
        for (int c = 0; c < 4; c++)
            #pragma unroll
            for (int e = 0; e < 4; e++) acc[a][c][e] = 0.f;

    auto produce = [&](int ch, char* stg) {
        // W tile: linear cp.async copy (layout identical gmem -> smem)
        {
            const uint32_t wdst = smem_u32(stg + 16384) + tid * 16;
            const uint8_t* wsrc = wtiles + (size_t)ch * 16384 + tid * 16;
            #pragma unroll
            for (int i = 0; i < 4; i++)
                CP_ASYNC16(wdst + i * 4096, wsrc + i * 4096);
            CP_COMMIT();
        }
        // A' = q .* k, split hi/lo, stored in A-fragment layout
        char* Ah = stg;
        char* Al = stg + 8192;
        const float4* kc = kp + ch * 8;
        const float4* qc = qp + ch * 8;
        const uint32_t blk = (uint32_t)((sh * 8 + mt_p) * 32) * 16;
        #pragma unroll
        for (int g = 0; g < 4; g++) {
            float4 kv = kc[g];
            float4 qv = __ldg(qc + g);
            float x0 = kv.x * qv.x, x1 = kv.y * qv.y;
            float x2 = kv.z * qv.z, x3 = kv.w * qv.w;
            #pragma unroll
            for (int e = 0; e < 2; e++) {
                const int pl = g * 2 + e;                 // k-pair 0..7
                uint32_t h, l;
                if (e == 0) split2(x0, x1, h, l);
                else        split2(x2, x3, h, l);
                const uint32_t areg = (uint32_t)(((pl >> 2) << 1) | reg_hi);
                const uint32_t off  = blk + (uint32_t)(lane_p + (pl & 3)) * 16 + areg * 4;
                *(uint32_t*)(Ah + off) = h;
                *(uint32_t*)(Al + off) = l;
            }
        }
    };

    auto consume = [&](const char* stg) {
        const char* Ahi = stg;
        const char* Alo = stg + 8192;
        const char* Whi = stg + 16384;
        const char* Wlo = stg + 24576;
        #pragma unroll
        for (int s = 0; s < 2; s++) {
            uint32_t a[4][4];
            #pragma unroll
            for (int mt = 0; mt < 4; mt++) {
                uint4 v4 = *(const uint4*)(Ahi + ((size_t)((s * 8 + mh * 4 + mt) * 32 + lane)) * 16);
                a[mt][0] = v4.x; a[mt][1] = v4.y; a[mt][2] = v4.z; a[mt][3] = v4.w;
            }
            uint32_t bh[4][2], bl[4][2];
            #pragma unroll
            for (int nf = 0; nf < 4; nf++) {
                uint2 u  = *(const uint2*)(Whi + ((size_t)((s * 16 + nq * 4 + nf) * 32 + lane)) * 8);
                uint2 u2 = *(const uint2*)(Wlo + ((size_t)((s * 16 + nq * 4 + nf) * 32 + lane)) * 8);
                bh[nf][0] = u.x;  bh[nf][1] = u.y;
                bl[nf][0] = u2.x; bl[nf][1] = u2.y;
            }
            #pragma unroll
            for (int mt = 0; mt < 4; mt++)
                #pragma unroll
                for (int nf = 0; nf < 4; nf++) {
                    MMA_BF16(acc[mt][nf], a[mt], bh[nf]);
                    MMA_BF16(acc[mt][nf], a[mt], bl[nf]);
                }
            #pragma unroll
            for (int mt = 0; mt < 4; mt++) {
                uint4 v4 = *(const uint4*)(Alo + ((size_t)((s * 8 + mh * 4 + mt) * 32 + lane)) * 16);
                a[mt][0] = v4.x; a[mt][1] = v4.y; a[mt][2] = v4.z; a[mt][3] = v4.w;
            }
            #pragma unroll
            for (int mt = 0; mt < 4; mt++)
                #pragma unroll
                for (int nf = 0; nf < 4; nf++)
                    MMA_BF16(acc[mt][nf], a[mt], bh[nf]);
        }
    };

    char* buf0 = sm;
    char* buf1 = sm + STAGE_SZ;

    produce(0, buf0);
    CP_WAIT0();
    __syncthreads();

    for (int ch = 0; ch < NCHUNK; ch++) {
        char* cur = (ch & 1) ? buf1 : buf0;
        char* nxt = (ch & 1) ? buf0 : buf1;
        if (ch < NCHUNK - 1) produce(ch + 1, nxt);
        consume(cur);
        CP_WAIT0();
        __syncthreads();
    }

    // epilogue
    const size_t rowbase = (size_t)bi * 128;
    const int colbase = nt * 128 + nq * 32 + (lane & 3) * 2;
    #pragma unroll
    for (int mt = 0; mt < 4; mt++) {
        const int j0 = mh * 64 + mt * 16 + (lane >> 2);
        #pragma unroll
        for (int nf = 0; nf < 4; nf++) {
            const int col = colbase + nf * 8;
            float* p0 = out + OFF_LOGITS + (rowbase + j0) * (size_t)VV + col;
            float* p1 = out + OFF_LOGITS + (rowbase + j0 + 8) * (size_t)VV + col;
            *(float2*)p0 = make_float2(acc[mt][nf][0], acc[mt][nf][1]);
            *(float2*)p1 = make_float2(acc[mt][nf][2], acc[mt][nf][3]);
        }
    }
}

// ---------------------------------------------------------------------------
// Mask kernels
// ---------------------------------------------------------------------------
__global__ void span_kernel(const int* __restrict__ mask_idx, float* __restrict__ out)
{
    const int b = blockIdx.x;
    const int t = threadIdx.x;
    __shared__ int mi[Msz];
    if (t < Msz) mi[t] = mask_idx[b * Msz + t];
    __syncthreads();
    int in = 0;
    #pragma unroll 8
    for (int m = 0; m < Msz; m++) in |= (mi[m] == t);
    g_span[b * Lsz + t] = in;
    out[OFF_MASKAA + (size_t)b * Lsz + t] = (float)in;
}

__global__ void diag_kernel(float* __restrict__ out)
{
    const int t = blockIdx.x * 256 + threadIdx.x;
    const int r = t & (Msz * Msz - 1);
    const int i = r >> 7, j = r & 127;
    out[OFF_DIAG + t] = (i == j) ? 1.0f : 0.0f;
}

__global__ void pair_kernel(float* __restrict__ out)
{
    const int idx = blockIdx.x * 256 + threadIdx.x;
    const int b   = idx >> 18;
    const int rem = idx & 262143;
    const int l1  = rem >> 8;
    const int l2g = (rem & 255) * 4;
    const float s1 = (float)g_span[b * Lsz + l1];
    const int* sp = g_span + b * Lsz + l2g;
    float4 o;
    o.x = s1 * sp[0]; o.y = s1 * sp[1]; o.z = s1 * sp[2]; o.w = s1 * sp[3];
    ((float4*)(out + OFF_PAIR))[idx] = o;
}

// ---------------------------------------------------------------------------
// Launch
// ---------------------------------------------------------------------------
extern "C" void kernel_launch(void* const* d_in, const int* in_sizes, int n_in,
                              void* d_out, int out_size)
{
    const float* x_enc    = (const float*)d_in[0];
    const float* ln_gamma = (const float*)d_in[1];
    const float* ln_beta  = (const float*)d_in[2];
    const float* Wq       = (const float*)d_in[3];
    const float* Wk       = (const float*)d_in[4];
    const float* W_embed  = (const float*)d_in[5];
    const float* W_mlm    = (const float*)d_in[6];
    const int*   mask_idx = (const int*)d_in[7];
    float* out = (float*)d_out;

    cudaFuncSetAttribute(logits_mma_kernel,
                         cudaFuncAttributeMaxDynamicSharedMemorySize, SMEM_MMA);

    wsplit_kernel<<<dim3(NCHUNK, 8), 256>>>(W_embed);
    ln_mlm_kernel<<<Bsz * Lsz, 256>>>(x_enc, ln_gamma, ln_beta, W_mlm, out);
    gather_kernel<<<Bsz * Msz, 256>>>(mask_idx);
    qk_gemm_kernel<<<dim3(8, 8, 2), 256>>>(Wq, Wk);
    logits_mma_kernel<<<dim3(8, Bsz * Msz), 256, SMEM_MMA>>>(out);
    span_kernel<<<Bsz, Lsz>>>(mask_idx, out);
    diag_kernel<<<(Bsz * Msz * Msz) / 256, 256>>>(out);
    pair_kernel<<<(Bsz * Lsz * Lsz / 4) / 256, 256>>>(out);
}

// round 8
// speedup vs baseline: 4.5135x; 2.0481x over previous
#include <cuda_runtime.h>
#include <cuda_fp16.h>
#include <cstdint>
#include <cstddef>

// ---------------------------------------------------------------------------
// Problem constants
// ---------------------------------------------------------------------------
#define Bsz 8
#define Lsz 1024
#define Hsz 1024
#define Msz 128
#define Vsz 32
#define VV  (Vsz * Vsz)          // 1024
#define LN_EPS 1e-5f
#define NCHUNK 32                // K chunks of 32

// Output layout offsets (floats)
static const size_t OFF_LOGITS = 0;
static const size_t OFF_MLM    = 134217728;
static const size_t OFF_DIAG   = OFF_MLM + (size_t)Bsz * Lsz * Vsz;
static const size_t OFF_MASKAA = OFF_DIAG + (size_t)Bsz * Msz * Msz;
static const size_t OFF_PAIR   = OFF_MASKAA + (size_t)Bsz * Lsz;

// ---------------------------------------------------------------------------
// Device scratch
// ---------------------------------------------------------------------------
__device__ float g_xnorm[(size_t)Bsz * Lsz * Hsz];   // 32 MB
__device__ float g_xm[(size_t)Bsz * Msz * Hsz];      // 4 MB
__device__ float g_q [(size_t)Bsz * Msz * Hsz];      // 4 MB
__device__ float g_k [(size_t)Bsz * Msz * Hsz];      // 4 MB
__device__ int   g_span[Bsz * Lsz];
// W_embed split hi/lo fp16 in mma B-fragment layout per (ntile, chunk):
// [nt(8)][chunk(32)] x 16KB tile = [hi 8KB | lo 8KB]
// within hi/lo: addr = ((s*16 + nf)*32 + lane)*8 + breg*4
__device__ __align__(1024) uint8_t g_Wt[8 * NCHUNK * 16384];     // 4 MB
// A' = q (.) k, single-rounded fp16, mma A-fragment layout per (bi, chunk):
// [bi(1024)][chunk(32)] x 8KB ; addr = ((s*8 + mtile)*32 + lane)*16 + areg*4
__device__ __align__(1024) uint8_t g_At[(size_t)1024 * NCHUNK * 8192]; // 256 MB

// ---------------------------------------------------------------------------
// Helpers
// ---------------------------------------------------------------------------
__device__ __forceinline__ uint32_t smem_u32(const void* p) {
    uint32_t a;
    asm("{ .reg .u64 t; cvta.to.shared.u64 t, %1; cvt.u32.u64 %0, t; }"
        : "=r"(a) : "l"(p));
    return a;
}

// pack two fp32 into f16x2 (first arg in low 16 bits)
__device__ __forceinline__ uint32_t pack_f16(float lo, float hi) {
    uint32_t r;
    asm("cvt.rn.f16x2.f32 %0, %1, %2;" : "=r"(r) : "f"(hi), "f"(lo));
    return r;
}
// split pair (x0,x1) into hi f16x2 + residual-lo f16x2
__device__ __forceinline__ void split2_f16(float x0, float x1, uint32_t& h, uint32_t& l) {
    h = pack_f16(x0, x1);
    float h0, h1;
    asm("{.reg .f16 a,b; mov.b32 {a,b}, %2; cvt.f32.f16 %0, a; cvt.f32.f16 %1, b;}"
        : "=f"(h0), "=f"(h1) : "r"(h));
    l = pack_f16(x0 - h0, x1 - h1);
}

#define CP_ASYNC16(dst_u32, src_ptr) \
    asm volatile("cp.async.cg.shared.global [%0], [%1], 16;" \
                 :: "r"(dst_u32), "l"(src_ptr) : "memory")
#define CP_COMMIT()  asm volatile("cp.async.commit_group;" ::: "memory")
#define CP_WAIT0()   asm volatile("cp.async.wait_group 0;" ::: "memory")

#define MMA_F16(c, a, bb) \
    asm volatile("mma.sync.aligned.m16n8k16.row.col.f32.f16.f16.f32 " \
                 "{%0,%1,%2,%3},{%4,%5,%6,%7},{%8,%9},{%0,%1,%2,%3};" \
                 : "+f"((c)[0]), "+f"((c)[1]), "+f"((c)[2]), "+f"((c)[3]) \
                 : "r"((a)[0]), "r"((a)[1]), "r"((a)[2]), "r"((a)[3]), \
                   "r"((bb)[0]), "r"((bb)[1]))

// ---------------------------------------------------------------------------
// Kernel 0: split W_embed into fp16 hi/lo in mma B-fragment layout.
// grid (32 chunks, 8 ntiles) x 256 threads.
// ---------------------------------------------------------------------------
__global__ __launch_bounds__(256) void wsplit_kernel(const float* __restrict__ W)
{
    const int ch = blockIdx.x, nt = blockIdx.y, tid = threadIdx.x;
    const int v  = tid >> 1;              // 0..127 (n within tile)
    const int sh = tid & 1;               // k16 step within chunk32
    const int hbase = ch * 32 + sh * 16;
    const float4* src = (const float4*)(W + (size_t)(nt * 128 + v) * Hsz + hbase);
    uint8_t* tile = g_Wt + (size_t)(nt * NCHUNK + ch) * 16384;
    const int nf = v >> 3;
    const int lbase = (v & 7) * 4;
    #pragma unroll
    for (int g = 0; g < 4; g++) {
        float4 x = src[g];
        #pragma unroll
        for (int e = 0; e < 2; e++) {
            const int pl = g * 2 + e;     // k-pair 0..7 within k16
            uint32_t h, l;
            if (e == 0) split2_f16(x.x, x.y, h, l);
            else        split2_f16(x.z, x.w, h, l);
            const uint32_t off =
                (uint32_t)(((sh * 16 + nf) * 32 + lbase + (pl & 3)) * 8 + (pl >> 2) * 4);
            *(uint32_t*)(tile + off)        = h;
            *(uint32_t*)(tile + 8192 + off) = l;
        }
    }
}

// ---------------------------------------------------------------------------
// Kernel A: build A' = q (.) k as fp16 in mma A-fragment layout (per bi).
// grid (1024 bi) x 256 threads. Coalesced uint4 stores.
// ---------------------------------------------------------------------------
__global__ __launch_bounds__(256) void asplit_kernel()
{
    const int bi = blockIdx.x;
    const int b  = bi >> 7;
    const int tid = threadIdx.x;
    const int mtile = tid >> 5;           // 0..7
    const int lane  = tid & 31;
    const int j0 = mtile * 16 + (lane >> 2);
    const int j1 = j0 + 8;
    const int kq = (lane & 3) * 2;

    const float* qrow = g_q + (size_t)bi * Hsz;
    const float* k0r  = g_k + (size_t)(b * Msz + j0) * Hsz;
    const float* k1r  = g_k + (size_t)(b * Msz + j1) * Hsz;
    uint8_t* outb = g_At + (size_t)bi * (NCHUNK * 8192);

    for (int ch = 0; ch < NCHUNK; ch++) {
        #pragma unroll
        for (int s = 0; s < 2; s++) {
            const int kk = ch * 32 + s * 16 + kq;
            float2 qa  = *(const float2*)(qrow + kk);
            float2 qb  = *(const float2*)(qrow + kk + 8);
            float2 k0a = *(const float2*)(k0r + kk);
            float2 k0b = *(const float2*)(k0r + kk + 8);
            float2 k1a = *(const float2*)(k1r + kk);
            float2 k1b = *(const float2*)(k1r + kk + 8);
            uint4 o;
            o.x = pack_f16(k0a.x * qa.x, k0a.y * qa.y);   // areg0: (j0, k, k+1)
            o.y = pack_f16(k1a.x * qa.x, k1a.y * qa.y);   // areg1: (j0+8, k, k+1)
            o.z = pack_f16(k0b.x * qb.x, k0b.y * qb.y);   // areg2: (j0, k+8, k+9)
            o.w = pack_f16(k1b.x * qb.x, k1b.y * qb.y);   // areg3: (j0+8, k+8, k+9)
            *(uint4*)(outb + (size_t)ch * 8192
                       + (size_t)(((s * 8 + mtile) * 32 + lane) * 16)) = o;
        }
    }
}

// ---------------------------------------------------------------------------
// Kernel 1: LayerNorm + fused MLM logits (vectorized MLM loop)
// ---------------------------------------------------------------------------
__global__ __launch_bounds__(256) void ln_mlm_kernel(
    const float* __restrict__ x, const float* __restrict__ gamma,
    const float* __restrict__ beta, const float* __restrict__ wmlm,
    float* __restrict__ out)
{
    const int row = blockIdx.x;
    const int t   = threadIdx.x;
    __shared__ float sx[Hsz];
    __shared__ float red[16];
    __shared__ float s_mu, s_rs;

    const float4* xr = (const float4*)(x + (size_t)row * Hsz);
    float4 v = xr[t];
    float s  = v.x + v.y + v.z + v.w;
    float ss = v.x*v.x + v.y*v.y + v.z*v.z + v.w*v.w;
    #pragma unroll
    for (int o = 16; o; o >>= 1) {
        s  += __shfl_xor_sync(0xffffffffu, s,  o);
        ss += __shfl_xor_sync(0xffffffffu, ss, o);
    }
    if ((t & 31) == 0) { red[t >> 5] = s; red[8 + (t >> 5)] = ss; }
    __syncthreads();
    if (t == 0) {
        float a = 0.f, b2 = 0.f;
        #pragma unroll
        for (int i = 0; i < 8; i++) { a += red[i]; b2 += red[8 + i]; }
        float mu  = a * (1.0f / Hsz);
        float var = b2 * (1.0f / Hsz) - mu * mu;
        s_mu = mu;
        s_rs = rsqrtf(var + LN_EPS);
    }
    __syncthreads();
    const float mu = s_mu, rs = s_rs;
    float4 g4 = ((const float4*)gamma)[t];
    float4 b4 = ((const float4*)beta)[t];
    float4 n;
    n.x = (v.x - mu) * rs * g4.x + b4.x;
    n.y = (v.y - mu) * rs * g4.y + b4.y;
    n.z = (v.z - mu) * rs * g4.z + b4.z;
    n.w = (v.w - mu) * rs * g4.w + b4.w;
    ((float4*)(g_xnorm + (size_t)row * Hsz))[t] = n;
    ((float4*)sx)[t] = n;
    __syncthreads();

    const int w = t >> 5, lane = t & 31;
    float p0 = 0.f, p1 = 0.f, p2 = 0.f, p3 = 0.f;
    const float4* sx4 = (const float4*)sx;
    const float4* w04 = (const float4*)(wmlm + (size_t)(w * 4 + 0) * Hsz);
    const float4* w14 = (const float4*)(wmlm + (size_t)(w * 4 + 1) * Hsz);
    const float4* w24 = (const float4*)(wmlm + (size_t)(w * 4 + 2) * Hsz);
    const float4* w34 = (const float4*)(wmlm + (size_t)(w * 4 + 3) * Hsz);
    #pragma unroll 4
    for (int h = lane; h < Hsz / 4; h += 32) {
        float4 xv = sx4[h];
        float4 a0 = __ldg(w04 + h);
        float4 a1 = __ldg(w14 + h);
        float4 a2 = __ldg(w24 + h);
        float4 a3 = __ldg(w34 + h);
        p0 += xv.x*a0.x + xv.y*a0.y + xv.z*a0.z + xv.w*a0.w;
        p1 += xv.x*a1.x + xv.y*a1.y + xv.z*a1.z + xv.w*a1.w;
        p2 += xv.x*a2.x + xv.y*a2.y + xv.z*a2.z + xv.w*a2.w;
        p3 += xv.x*a3.x + xv.y*a3.y + xv.z*a3.z + xv.w*a3.w;
    }
    #pragma unroll
    for (int o = 16; o; o >>= 1) {
        p0 += __shfl_xor_sync(0xffffffffu, p0, o);
        p1 += __shfl_xor_sync(0xffffffffu, p1, o);
        p2 += __shfl_xor_sync(0xffffffffu, p2, o);
        p3 += __shfl_xor_sync(0xffffffffu, p3, o);
    }
    if (lane == 0) {
        float* dst = out + OFF_MLM + (size_t)row * Vsz + w * 4;
        dst[0] = p0; dst[1] = p1; dst[2] = p2; dst[3] = p3;
    }
}

// ---------------------------------------------------------------------------
// Kernel 2: gather masked rows
// ---------------------------------------------------------------------------
__global__ __launch_bounds__(256) void gather_kernel(const int* __restrict__ mask_idx)
{
    const int g = blockIdx.x;
    const int b = g >> 7;
    const int src = mask_idx[g];
    const float4* s = (const float4*)(g_xnorm + ((size_t)(b * Lsz + src)) * Hsz);
    float4* d = (float4*)(g_xm + (size_t)g * Hsz);
    d[threadIdx.x] = s[threadIdx.x];
}

// ---------------------------------------------------------------------------
// fp32 SGEMM body (q/k projections)
// ---------------------------------------------------------------------------
__device__ __forceinline__ void sgemm_body_128(
    const float* __restrict__ A, const float* __restrict__ Bm,
    float* __restrict__ C, int ldc)
{
    __shared__ float As[8][128];
    __shared__ float Bs[8][128];
    const int tid = threadIdx.x;
    const int tx = tid & 15, ty = tid >> 4;
    const int lr = tid >> 1;
    const int lk = (tid & 1) * 4;

    float acc[8][8];
    #pragma unroll
    for (int r = 0; r < 8; r++)
        #pragma unroll
        for (int c = 0; c < 8; c++) acc[r][c] = 0.f;

    for (int k0 = 0; k0 < Hsz; k0 += 8) {
        float4 av = *(const float4*)(A + (size_t)lr * Hsz + k0 + lk);
        float4 bv = *(const float4*)(Bm + (size_t)lr * Hsz + k0 + lk);
        As[lk + 0][lr] = av.x; As[lk + 1][lr] = av.y;
        As[lk + 2][lr] = av.z; As[lk + 3][lr] = av.w;
        Bs[lk + 0][lr] = bv.x; Bs[lk + 1][lr] = bv.y;
        Bs[lk + 2][lr] = bv.z; Bs[lk + 3][lr] = bv.w;
        __syncthreads();
        #pragma unroll
        for (int kk = 0; kk < 8; kk++) {
            float a[8], bb[8];
            *(float4*)(a)      = *(const float4*)&As[kk][ty * 4];
            *(float4*)(a + 4)  = *(const float4*)&As[kk][64 + ty * 4];
            *(float4*)(bb)     = *(const float4*)&Bs[kk][tx * 4];
            *(float4*)(bb + 4) = *(const float4*)&Bs[kk][64 + tx * 4];
            #pragma unroll
            for (int r = 0; r < 8; r++)
                #pragma unroll
                for (int c = 0; c < 8; c++)
                    acc[r][c] = fmaf(a[r], bb[c], acc[r][c]);
        }
        __syncthreads();
    }
    #pragma unroll
    for (int r = 0; r < 8; r++) {
        const int row = (r < 4) ? (ty * 4 + r) : (64 + ty * 4 + (r - 4));
        *(float4*)(C + (size_t)row * ldc + tx * 4)      = make_float4(acc[r][0], acc[r][1], acc[r][2], acc[r][3]);
        *(float4*)(C + (size_t)row * ldc + 64 + tx * 4) = make_float4(acc[r][4], acc[r][5], acc[r][6], acc[r][7]);
    }
}

__global__ __launch_bounds__(256, 2) void qk_gemm_kernel(
    const float* __restrict__ Wq, const float* __restrict__ Wk)
{
    const float* Bmat = blockIdx.z ? Wk : Wq;
    float* Cbase      = blockIdx.z ? g_k : g_q;
    const int rowBase = blockIdx.y * 128;
    const int colBase = blockIdx.x * 128;
    sgemm_body_128(g_xm + (size_t)rowBase * Hsz, Bmat + (size_t)colBase * Hsz,
                   Cbase + (size_t)rowBase * Hsz + colBase, Hsz);
}

// ---------------------------------------------------------------------------
// Kernel 4: logits contraction, fp16 2-pass (A single-rounded, W exact split).
// grid (8 vtiles, 1024 bi), 256 threads, 2 CTA/SM.
// Per chunk: pure cp.async (A 8KB + W 16KB), consumer mma only.
// stage 24KB: [A 8K][Whi 8K][Wlo 8K], double buffered (48KB).
// ---------------------------------------------------------------------------
#define STAGE_SZ 24576
#define SMEM_MMA (2 * STAGE_SZ)

__global__ __launch_bounds__(256, 2) void logits_mma_kernel(float* __restrict__ out)
{
    extern __shared__ char sm[];
    const int tid = threadIdx.x;
    const int nt  = blockIdx.x;          // v-tile 0..7
    const int bi  = blockIdx.y;          // 0..1023 == b*128 + i
    const int w    = tid >> 5, lane = tid & 31;
    const int mh   = w & 1;              // m-half (0: j 0-63, 1: j 64-127)
    const int nq   = w >> 1;             // n-quarter (32 cols)

    const uint8_t* atiles = g_At + (size_t)bi * (NCHUNK * 8192);
    const uint8_t* wtiles = g_Wt + (size_t)nt * (NCHUNK * 16384);

    float acc[4][4][4];
    #pragma unroll
    for (int a = 0; a < 4; a++)
        #pragma unroll
        for (int c = 0; c < 4; c++)
            #pragma unroll
            for (int e = 0; e < 4; e++) acc[a][c][e] = 0.f;

    auto produce = [&](int ch, char* stg) {
        const uint32_t dA = smem_u32(stg) + tid * 32;
        const uint8_t* sA = atiles + (size_t)ch * 8192 + tid * 32;
        CP_ASYNC16(dA,      sA);
        CP_ASYNC16(dA + 16, sA + 16);
        const uint32_t dW = smem_u32(stg + 8192) + tid * 16;
        const uint8_t* sW = wtiles + (size_t)ch * 16384 + tid * 16;
        #pragma unroll
        for (int i = 0; i < 4; i++)
            CP_ASYNC16(dW + i * 4096, sW + i * 4096);
        CP_COMMIT();
    };

    auto consume = [&](const char* stg) {
        const char* Ah = stg;
        const char* Wh = stg + 8192;
        const char* Wl = stg + 16384;
        #pragma unroll
        for (int s = 0; s < 2; s++) {
            uint32_t a[4][4];
            #pragma unroll
            for (int mt = 0; mt < 4; mt++) {
                uint4 v4 = *(const uint4*)(Ah + ((size_t)((s * 8 + mh * 4 + mt) * 32 + lane)) * 16);
                a[mt][0] = v4.x; a[mt][1] = v4.y; a[mt][2] = v4.z; a[mt][3] = v4.w;
            }
            uint32_t bh[4][2], bl[4][2];
            #pragma unroll
            for (int nf = 0; nf < 4; nf++) {
                uint2 u  = *(const uint2*)(Wh + ((size_t)((s * 16 + nq * 4 + nf) * 32 + lane)) * 8);
                uint2 u2 = *(const uint2*)(Wl + ((size_t)((s * 16 + nq * 4 + nf) * 32 + lane)) * 8);
                bh[nf][0] = u.x;  bh[nf][1] = u.y;
                bl[nf][0] = u2.x; bl[nf][1] = u2.y;
            }
            #pragma unroll
            for (int mt = 0; mt < 4; mt++)
                #pragma unroll
                for (int nf = 0; nf < 4; nf++) {
                    MMA_F16(acc[mt][nf], a[mt], bh[nf]);
                    MMA_F16(acc[mt][nf], a[mt], bl[nf]);
                }
        }
    };

    char* buf0 = sm;
    char* buf1 = sm + STAGE_SZ;

    produce(0, buf0);
    CP_WAIT0();
    __syncthreads();

    for (int ch = 0; ch < NCHUNK; ch++) {
        char* cur = (ch & 1) ? buf1 : buf0;
        char* nxt = (ch & 1) ? buf0 : buf1;
        if (ch < NCHUNK - 1) produce(ch + 1, nxt);
        consume(cur);
        CP_WAIT0();
        __syncthreads();
    }

    // epilogue
    const size_t rowbase = (size_t)bi * 128;
    const int colbase = nt * 128 + nq * 32 + (lane & 3) * 2;
    #pragma unroll
    for (int mt = 0; mt < 4; mt++) {
        const int j0 = mh * 64 + mt * 16 + (lane >> 2);
        #pragma unroll
        for (int nf = 0; nf < 4; nf++) {
            const int col = colbase + nf * 8;
            float* p0 = out + OFF_LOGITS + (rowbase + j0) * (size_t)VV + col;
            float* p1 = out + OFF_LOGITS + (rowbase + j0 + 8) * (size_t)VV + col;
            *(float2*)p0 = make_float2(acc[mt][nf][0], acc[mt][nf][1]);
            *(float2*)p1 = make_float2(acc[mt][nf][2], acc[mt][nf][3]);
        }
    }
}

// ---------------------------------------------------------------------------
// Mask kernels
// ---------------------------------------------------------------------------
__global__ void span_kernel(const int* __restrict__ mask_idx, float* __restrict__ out)
{
    const int b = blockIdx.x;
    const int t = threadIdx.x;
    __shared__ int mi[Msz];
    if (t < Msz) mi[t] = mask_idx[b * Msz + t];
    __syncthreads();
    int in = 0;
    #pragma unroll 8
    for (int m = 0; m < Msz; m++) in |= (mi[m] == t);
    g_span[b * Lsz + t] = in;
    out[OFF_MASKAA + (size_t)b * Lsz + t] = (float)in;
}

__global__ void diag_kernel(float* __restrict__ out)
{
    const int t = blockIdx.x * 256 + threadIdx.x;
    const int r = t & (Msz * Msz - 1);
    const int i = r >> 7, j = r & 127;
    out[OFF_DIAG + t] = (i == j) ? 1.0f : 0.0f;
}

__global__ void pair_kernel(float* __restrict__ out)
{
    const int idx = blockIdx.x * 256 + threadIdx.x;
    const int b   = idx >> 18;
    const int rem = idx & 262143;
    const int l1  = rem >> 8;
    const int l2g = (rem & 255) * 4;
    const float s1 = (float)g_span[b * Lsz + l1];
    const int* sp = g_span + b * Lsz + l2g;
    float4 o;
    o.x = s1 * sp[0]; o.y = s1 * sp[1]; o.z = s1 * sp[2]; o.w = s1 * sp[3];
    ((float4*)(out + OFF_PAIR))[idx] = o;
}

// ---------------------------------------------------------------------------
// Launch
// ---------------------------------------------------------------------------
extern "C" void kernel_launch(void* const* d_in, const int* in_sizes, int n_in,
                              void* d_out, int out_size)
{
    const float* x_enc    = (const float*)d_in[0];
    const float* ln_gamma = (const float*)d_in[1];
    const float* ln_beta  = (const float*)d_in[2];
    const float* Wq       = (const float*)d_in[3];
    const float* Wk       = (const float*)d_in[4];
    const float* W_embed  = (const float*)d_in[5];
    const float* W_mlm    = (const float*)d_in[6];
    const int*   mask_idx = (const int*)d_in[7];
    float* out = (float*)d_out;

    cudaFuncSetAttribute(logits_mma_kernel,
                         cudaFuncAttributeMaxDynamicSharedMemorySize, SMEM_MMA);

    wsplit_kernel<<<dim3(NCHUNK, 8), 256>>>(W_embed);
    ln_mlm_kernel<<<Bsz * Lsz, 256>>>(x_enc, ln_gamma, ln_beta, W_mlm, out);
    gather_kernel<<<Bsz * Msz, 256>>>(mask_idx);
    qk_gemm_kernel<<<dim3(8, 8, 2), 256>>>(Wq, Wk);
    asplit_kernel<<<1024, 256>>>();
    logits_mma_kernel<<<dim3(8, Bsz * Msz), 256, SMEM_MMA>>>(out);
    span_kernel<<<Bsz, Lsz>>>(mask_idx, out);
    diag_kernel<<<(Bsz * Msz * Msz) / 256, 256>>>(out);
    pair_kernel<<<(Bsz * Lsz * Lsz / 4) / 256, 256>>>(out);
}

// round 9
// speedup vs baseline: 6.1495x; 1.3625x over previous
#include <cuda_runtime.h>
#include <cuda_fp16.h>
#include <cstdint>
#include <cstddef>

// ---------------------------------------------------------------------------
// Problem constants
// ---------------------------------------------------------------------------
#define Bsz 8
#define Lsz 1024
#define Hsz 1024
#define Msz 128
#define Vsz 32
#define VV  (Vsz * Vsz)          // 1024
#define LN_EPS 1e-5f
#define NCHUNK 32                // K chunks of 32

// Output layout offsets (floats)
static const size_t OFF_LOGITS = 0;
static const size_t OFF_MLM    = 134217728;
static const size_t OFF_DIAG   = OFF_MLM + (size_t)Bsz * Lsz * Vsz;
static const size_t OFF_MASKAA = OFF_DIAG + (size_t)Bsz * Msz * Msz;
static const size_t OFF_PAIR   = OFF_MASKAA + (size_t)Bsz * Lsz;

// ---------------------------------------------------------------------------
// Device scratch
// ---------------------------------------------------------------------------
__device__ float g_xnorm[(size_t)Bsz * Lsz * Hsz];   // 32 MB
__device__ float g_xm[(size_t)Bsz * Msz * Hsz];      // 4 MB
__device__ float g_q [(size_t)Bsz * Msz * Hsz];      // 4 MB
__device__ float g_k [(size_t)Bsz * Msz * Hsz];      // 4 MB
__device__ int   g_span[Bsz * Lsz];

// W_embed fp16 (single-rounded), mma B-frag paired-nf layout per (nt, chunk):
// [nt(8)][chunk(32)] x 8KB ; addr = ((s*8 + nfp)*32 + lane)*16 + half*8 + breg*4
__device__ __align__(1024) uint8_t g_Wt[8 * NCHUNK * 8192];            // 2 MB
// Wq/Wk split hi/lo fp16, paired-nf B-frag layout:
// [mat(2)][ot(8)][chunk(32)] x 16KB = [hi 8KB | lo 8KB]
__device__ __align__(1024) uint8_t g_Wqk[2 * 8 * NCHUNK * 16384];      // 8 MB
// xm single-rounded fp16, mma A-frag layout: [mtile(8)][chunk(32)] x 8KB
// addr = ((s*8 + mt16)*32 + lane)*16 + areg*4
__device__ __align__(1024) uint8_t g_Xt[8 * NCHUNK * 8192];            // 2 MB
// A' = q (.) k fp16, mma A-frag layout per (bi, chunk): [bi(1024)][chunk(32)] x 8KB
__device__ __align__(1024) uint8_t g_At[(size_t)1024 * NCHUNK * 8192]; // 256 MB

// ---------------------------------------------------------------------------
// Helpers
// ---------------------------------------------------------------------------
__device__ __forceinline__ uint32_t smem_u32(const void* p) {
    uint32_t a;
    asm("{ .reg .u64 t; cvta.to.shared.u64 t, %1; cvt.u32.u64 %0, t; }"
        : "=r"(a) : "l"(p));
    return a;
}

// pack two fp32 into f16x2 (first arg in low 16 bits)
__device__ __forceinline__ uint32_t pack_f16(float lo, float hi) {
    uint32_t r;
    asm("cvt.rn.f16x2.f32 %0, %1, %2;" : "=r"(r) : "f"(hi), "f"(lo));
    return r;
}
// split pair (x0,x1) into hi f16x2 + residual-lo f16x2
__device__ __forceinline__ void split2_f16(float x0, float x1, uint32_t& h, uint32_t& l) {
    h = pack_f16(x0, x1);
    float h0, h1;
    asm("{.reg .f16 a,b; mov.b32 {a,b}, %2; cvt.f32.f16 %0, a; cvt.f32.f16 %1, b;}"
        : "=f"(h0), "=f"(h1) : "r"(h));
    l = pack_f16(x0 - h0, x1 - h1);
}

#define CP_ASYNC16(dst_u32, src_ptr) \
    asm volatile("cp.async.cg.shared.global [%0], [%1], 16;" \
                 :: "r"(dst_u32), "l"(src_ptr) : "memory")
#define CP_COMMIT()  asm volatile("cp.async.commit_group;" ::: "memory")
#define CP_WAIT0()   asm volatile("cp.async.wait_group 0;" ::: "memory")
#define CP_WAIT1()   asm volatile("cp.async.wait_group 1;" ::: "memory")

#define MMA_F16(c, a, bb) \
    asm volatile("mma.sync.aligned.m16n8k16.row.col.f32.f16.f16.f32 " \
                 "{%0,%1,%2,%3},{%4,%5,%6,%7},{%8,%9},{%0,%1,%2,%3};" \
                 : "+f"((c)[0]), "+f"((c)[1]), "+f"((c)[2]), "+f"((c)[3]) \
                 : "r"((a)[0]), "r"((a)[1]), "r"((a)[2]), "r"((a)[3]), \
                   "r"((bb)[0]), "r"((bb)[1]))

// ---------------------------------------------------------------------------
// Kernel 0a: W_embed -> fp16 B-frag (paired-nf) tiles. grid (32, 8) x 256.
// ---------------------------------------------------------------------------
__global__ __launch_bounds__(256) void wsplit_kernel(const float* __restrict__ W)
{
    const int ch = blockIdx.x, nt = blockIdx.y, tid = threadIdx.x;
    const int v  = tid >> 1;              // n within tile 0..127
    const int sh = tid & 1;               // k16 step
    const float4* src = (const float4*)(W + (size_t)(nt * 128 + v) * Hsz + ch * 32 + sh * 16);
    uint8_t* tile = g_Wt + (size_t)(nt * NCHUNK + ch) * 8192;
    const int nfp  = v >> 4;              // paired n-frag 0..7
    const int half = (v >> 3) & 1;
    const int lbase = (v & 7) * 4;
    #pragma unroll
    for (int g = 0; g < 4; g++) {
        float4 x = src[g];
        #pragma unroll
        for (int e = 0; e < 2; e++) {
            const int pl = g * 2 + e;     // k-pair 0..7
            uint32_t h = (e == 0) ? pack_f16(x.x, x.y) : pack_f16(x.z, x.w);
            const uint32_t off =
                (uint32_t)(((sh * 8 + nfp) * 32 + lbase + (pl & 3)) * 16 + half * 8 + (pl >> 2) * 4);
            *(uint32_t*)(tile + off) = h;
        }
    }
}

// ---------------------------------------------------------------------------
// Kernel 0b: Wq/Wk -> fp16 hi/lo B-frag (paired-nf). grid (32, 8, 2) x 256.
// ---------------------------------------------------------------------------
__global__ __launch_bounds__(256) void wqksplit_kernel(
    const float* __restrict__ Wq, const float* __restrict__ Wk)
{
    const int ch = blockIdx.x, ot = blockIdx.y, mat = blockIdx.z, tid = threadIdx.x;
    const float* W = mat ? Wk : Wq;
    const int v  = tid >> 1;
    const int sh = tid & 1;
    const float4* src = (const float4*)(W + (size_t)(ot * 128 + v) * Hsz + ch * 32 + sh * 16);
    uint8_t* tile = g_Wqk + (size_t)((mat * 8 + ot) * NCHUNK + ch) * 16384;
    const int nfp  = v >> 4;
    const int half = (v >> 3) & 1;
    const int lbase = (v & 7) * 4;
    #pragma unroll
    for (int g = 0; g < 4; g++) {
        float4 x = src[g];
        #pragma unroll
        for (int e = 0; e < 2; e++) {
            const int pl = g * 2 + e;
            uint32_t h, l;
            if (e == 0) split2_f16(x.x, x.y, h, l);
            else        split2_f16(x.z, x.w, h, l);
            const uint32_t off =
                (uint32_t)(((sh * 8 + nfp) * 32 + lbase + (pl & 3)) * 16 + half * 8 + (pl >> 2) * 4);
            *(uint32_t*)(tile + off)        = h;
            *(uint32_t*)(tile + 8192 + off) = l;
        }
    }
}

// ---------------------------------------------------------------------------
// Kernel 0c: xm -> fp16 A-frag tiles. grid (8 mtiles) x 256.
// ---------------------------------------------------------------------------
__global__ __launch_bounds__(256) void xmsplit_kernel()
{
    const int mt = blockIdx.x;
    const int tid = threadIdx.x;
    const int mt16 = tid >> 5;
    const int lane = tid & 31;
    const int j0 = mt * 128 + mt16 * 16 + (lane >> 2);
    const int j1 = j0 + 8;
    const int kq = (lane & 3) * 2;
    const float* x0 = g_xm + (size_t)j0 * Hsz;
    const float* x1 = g_xm + (size_t)j1 * Hsz;
    uint8_t* outb = g_Xt + (size_t)mt * (NCHUNK * 8192);

    for (int ch = 0; ch < NCHUNK; ch++) {
        #pragma unroll
        for (int s = 0; s < 2; s++) {
            const int kk = ch * 32 + s * 16 + kq;
            float2 a0 = *(const float2*)(x0 + kk);
            float2 a1 = *(const float2*)(x1 + kk);
            float2 b0 = *(const float2*)(x0 + kk + 8);
            float2 b1 = *(const float2*)(x1 + kk + 8);
            uint4 o;
            o.x = pack_f16(a0.x, a0.y);
            o.y = pack_f16(a1.x, a1.y);
            o.z = pack_f16(b0.x, b0.y);
            o.w = pack_f16(b1.x, b1.y);
            *(uint4*)(outb + (size_t)ch * 8192
                       + (size_t)(((s * 8 + mt16) * 32 + lane) * 16)) = o;
        }
    }
}

// ---------------------------------------------------------------------------
// Kernel A: A' = q (.) k fp16 A-frag per bi. grid (1024) x 256.
// ---------------------------------------------------------------------------
__global__ __launch_bounds__(256) void asplit_kernel()
{
    const int bi = blockIdx.x;
    const int b  = bi >> 7;
    const int tid = threadIdx.x;
    const int mtile = tid >> 5;
    const int lane  = tid & 31;
    const int j0 = mtile * 16 + (lane >> 2);
    const int j1 = j0 + 8;
    const int kq = (lane & 3) * 2;

    const float* qrow = g_q + (size_t)bi * Hsz;
    const float* k0r  = g_k + (size_t)(b * Msz + j0) * Hsz;
    const float* k1r  = g_k + (size_t)(b * Msz + j1) * Hsz;
    uint8_t* outb = g_At + (size_t)bi * (NCHUNK * 8192);

    for (int ch = 0; ch < NCHUNK; ch++) {
        #pragma unroll
        for (int s = 0; s < 2; s++) {
            const int kk = ch * 32 + s * 16 + kq;
            float2 qa  = *(const float2*)(qrow + kk);
            float2 qb  = *(const float2*)(qrow + kk + 8);
            float2 k0a = *(const float2*)(k0r + kk);
            float2 k0b = *(const float2*)(k0r + kk + 8);
            float2 k1a = *(const float2*)(k1r + kk);
            float2 k1b = *(const float2*)(k1r + kk + 8);
            uint4 o;
            o.x = pack_f16(k0a.x * qa.x, k0a.y * qa.y);
            o.y = pack_f16(k1a.x * qa.x, k1a.y * qa.y);
            o.z = pack_f16(k0b.x * qb.x, k0b.y * qb.y);
            o.w = pack_f16(k1b.x * qb.x, k1b.y * qb.y);
            *(uint4*)(outb + (size_t)ch * 8192
                       + (size_t)(((s * 8 + mtile) * 32 + lane) * 16)) = o;
        }
    }
}

// ---------------------------------------------------------------------------
// Kernel 1: LayerNorm + fused MLM logits
// ---------------------------------------------------------------------------
__global__ __launch_bounds__(256) void ln_mlm_kernel(
    const float* __restrict__ x, const float* __restrict__ gamma,
    const float* __restrict__ beta, const float* __restrict__ wmlm,
    float* __restrict__ out)
{
    const int row = blockIdx.x;
    const int t   = threadIdx.x;
    __shared__ float sx[Hsz];
    __shared__ float red[16];
    __shared__ float s_mu, s_rs;

    const float4* xr = (const float4*)(x + (size_t)row * Hsz);
    float4 v = xr[t];
    float s  = v.x + v.y + v.z + v.w;
    float ss = v.x*v.x + v.y*v.y + v.z*v.z + v.w*v.w;
    #pragma unroll
    for (int o = 16; o; o >>= 1) {
        s  += __shfl_xor_sync(0xffffffffu, s,  o);
        ss += __shfl_xor_sync(0xffffffffu, ss, o);
    }
    if ((t & 31) == 0) { red[t >> 5] = s; red[8 + (t >> 5)] = ss; }
    __syncthreads();
    if (t == 0) {
        float a = 0.f, b2 = 0.f;
        #pragma unroll
        for (int i = 0; i < 8; i++) { a += red[i]; b2 += red[8 + i]; }
        float mu  = a * (1.0f / Hsz);
        float var = b2 * (1.0f / Hsz) - mu * mu;
        s_mu = mu;
        s_rs = rsqrtf(var + LN_EPS);
    }
    __syncthreads();
    const float mu = s_mu, rs = s_rs;
    float4 g4 = ((const float4*)gamma)[t];
    float4 b4 = ((const float4*)beta)[t];
    float4 n;
    n.x = (v.x - mu) * rs * g4.x + b4.x;
    n.y = (v.y - mu) * rs * g4.y + b4.y;
    n.z = (v.z - mu) * rs * g4.z + b4.z;
    n.w = (v.w - mu) * rs * g4.w + b4.w;
    ((float4*)(g_xnorm + (size_t)row * Hsz))[t] = n;
    ((float4*)sx)[t] = n;
    __syncthreads();

    const int w = t >> 5, lane = t & 31;
    float p0 = 0.f, p1 = 0.f, p2 = 0.f, p3 = 0.f;
    const float4* sx4 = (const float4*)sx;
    const float4* w04 = (const float4*)(wmlm + (size_t)(w * 4 + 0) * Hsz);
    const float4* w14 = (const float4*)(wmlm + (size_t)(w * 4 + 1) * Hsz);
    const float4* w24 = (const float4*)(wmlm + (size_t)(w * 4 + 2) * Hsz);
    const float4* w34 = (const float4*)(wmlm + (size_t)(w * 4 + 3) * Hsz);
    #pragma unroll 4
    for (int h = lane; h < Hsz / 4; h += 32) {
        float4 xv = sx4[h];
        float4 a0 = __ldg(w04 + h);
        float4 a1 = __ldg(w14 + h);
        float4 a2 = __ldg(w24 + h);
        float4 a3 = __ldg(w34 + h);
        p0 += xv.x*a0.x + xv.y*a0.y + xv.z*a0.z + xv.w*a0.w;
        p1 += xv.x*a1.x + xv.y*a1.y + xv.z*a1.z + xv.w*a1.w;
        p2 += xv.x*a2.x + xv.y*a2.y + xv.z*a2.z + xv.w*a2.w;
        p3 += xv.x*a3.x + xv.y*a3.y + xv.z*a3.z + xv.w*a3.w;
    }
    #pragma unroll
    for (int o = 16; o; o >>= 1) {
        p0 += __shfl_xor_sync(0xffffffffu, p0, o);
        p1 += __shfl_xor_sync(0xffffffffu, p1, o);
        p2 += __shfl_xor_sync(0xffffffffu, p2, o);
        p3 += __shfl_xor_sync(0xffffffffu, p3, o);
    }
    if (lane == 0) {
        float* dst = out + OFF_MLM + (size_t)row * Vsz + w * 4;
        dst[0] = p0; dst[1] = p1; dst[2] = p2; dst[3] = p3;
    }
}

// ---------------------------------------------------------------------------
// Kernel 2: gather masked rows
// ---------------------------------------------------------------------------
__global__ __launch_bounds__(256) void gather_kernel(const int* __restrict__ mask_idx)
{
    const int g = blockIdx.x;
    const int b = g >> 7;
    const int src = mask_idx[g];
    const float4* s = (const float4*)(g_xnorm + ((size_t)(b * Lsz + src)) * Hsz);
    float4* d = (float4*)(g_xm + (size_t)g * Hsz);
    d[threadIdx.x] = s[threadIdx.x];
}

// ---------------------------------------------------------------------------
// Kernel 3: q/k projections via fp16 mma, 2-pass (Wq/Wk split, xm rounded).
// grid (8 ot, 8 mt, 2 mat), 256 threads.
// stage 24KB: [A 8K][Whi 8K][Wlo 8K] x 3 stages.
// ---------------------------------------------------------------------------
#define QK_STAGE 24576
#define QK_SMEM  (3 * QK_STAGE)

__global__ __launch_bounds__(256) void qk_mma_kernel()
{
    extern __shared__ char sm[];
    const int tid = threadIdx.x;
    const int ot  = blockIdx.x;
    const int mt  = blockIdx.y;
    const int mat = blockIdx.z;
    const int w    = tid >> 5, lane = tid & 31;
    const int mh   = w & 1;
    const int nq   = w >> 1;             // 0..3 -> 32 cols

    const uint8_t* atiles = g_Xt + (size_t)mt * (NCHUNK * 8192);
    const uint8_t* wtiles = g_Wqk + (size_t)((mat * 8 + ot) * NCHUNK) * 16384;
    float* outp = (mat ? g_k : g_q);

    float acc[4][4][4];
    #pragma unroll
    for (int a = 0; a < 4; a++)
        #pragma unroll
        for (int c = 0; c < 4; c++)
            #pragma unroll
            for (int e = 0; e < 4; e++) acc[a][c][e] = 0.f;

    auto produce = [&](int ch) {
        char* stg = sm + (ch % 3) * QK_STAGE;
        const uint32_t dA = smem_u32(stg) + tid * 32;
        const uint8_t* sA = atiles + (size_t)ch * 8192 + tid * 32;
        CP_ASYNC16(dA,      sA);
        CP_ASYNC16(dA + 16, sA + 16);
        const uint32_t dW = smem_u32(stg + 8192) + tid * 64;
        const uint8_t* sW = wtiles + (size_t)ch * 16384 + tid * 64;
        #pragma unroll
        for (int i = 0; i < 4; i++)
            CP_ASYNC16(dW + i * 16, sW + i * 16);
        CP_COMMIT();
    };

    auto consume = [&](int ch) {
        const char* stg = sm + (ch % 3) * QK_STAGE;
        const char* Ah = stg;
        const char* Wh = stg + 8192;
        const char* Wl = stg + 16384;
        #pragma unroll
        for (int s = 0; s < 2; s++) {
            uint32_t a[4][4];
            #pragma unroll
            for (int mtc = 0; mtc < 4; mtc++) {
                uint4 v4 = *(const uint4*)(Ah + ((size_t)((s * 8 + mh * 4 + mtc) * 32 + lane)) * 16);
                a[mtc][0] = v4.x; a[mtc][1] = v4.y; a[mtc][2] = v4.z; a[mtc][3] = v4.w;
            }
            uint32_t bh[4][2], bl[4][2];
            #pragma unroll
            for (int p = 0; p < 2; p++) {
                uint4 uh = *(const uint4*)(Wh + ((size_t)((s * 8 + nq * 2 + p) * 32 + lane)) * 16);
                uint4 ul = *(const uint4*)(Wl + ((size_t)((s * 8 + nq * 2 + p) * 32 + lane)) * 16);
                bh[p*2+0][0] = uh.x; bh[p*2+0][1] = uh.y;
                bh[p*2+1][0] = uh.z; bh[p*2+1][1] = uh.w;
                bl[p*2+0][0] = ul.x; bl[p*2+0][1] = ul.y;
                bl[p*2+1][0] = ul.z; bl[p*2+1][1] = ul.w;
            }
            #pragma unroll
            for (int mtc = 0; mtc < 4; mtc++)
                #pragma unroll
                for (int nf = 0; nf < 4; nf++) {
                    MMA_F16(acc[mtc][nf], a[mtc], bh[nf]);
                    MMA_F16(acc[mtc][nf], a[mtc], bl[nf]);
                }
        }
    };

    produce(0); produce(1);
    for (int ch = 0; ch < NCHUNK; ch++) {
        if (ch == NCHUNK - 1) { CP_WAIT0(); } else { CP_WAIT1(); }
        __syncthreads();
        if (ch + 2 < NCHUNK) produce(ch + 2);
        consume(ch);
    }

    // epilogue: write fp32 q/k
    const int colbase = ot * 128 + nq * 32 + (lane & 3) * 2;
    #pragma unroll
    for (int mtc = 0; mtc < 4; mtc++) {
        const int row = mt * 128 + mh * 64 + mtc * 16 + (lane >> 2);
        #pragma unroll
        for (int nf = 0; nf < 4; nf++) {
            const int col = colbase + nf * 8;
            *(float2*)(outp + (size_t)row * Hsz + col) =
                make_float2(acc[mtc][nf][0], acc[mtc][nf][1]);
            *(float2*)(outp + (size_t)(row + 8) * Hsz + col) =
                make_float2(acc[mtc][nf][2], acc[mtc][nf][3]);
        }
    }
}

// ---------------------------------------------------------------------------
// Kernel 4: logits contraction, 1-pass fp16, N=256 per CTA.
// grid (4 ntile-pairs, 1024 bi), 256 threads, 1 CTA/SM.
// stage 24KB: [A 8K][W0 8K][W1 8K] x 3 stages (72KB).
// ---------------------------------------------------------------------------
#define LG_STAGE 24576
#define LG_SMEM  (3 * LG_STAGE)

__global__ __launch_bounds__(256, 1) void logits_mma_kernel(float* __restrict__ out)
{
    extern __shared__ char sm[];
    const int tid = threadIdx.x;
    const int nt2 = blockIdx.x;          // 0..3 (256 v-cols)
    const int bi  = blockIdx.y;          // 0..1023
    const int w    = tid >> 5, lane = tid & 31;
    const int mh   = w & 1;              // j half
    const int nq   = w >> 1;             // 0..3 -> 64 cols

    const uint8_t* atiles = g_At + (size_t)bi * (NCHUNK * 8192);
    const uint8_t* w0tiles = g_Wt + (size_t)((nt2 * 2 + 0) * NCHUNK) * 8192;
    const uint8_t* w1tiles = g_Wt + (size_t)((nt2 * 2 + 1) * NCHUNK) * 8192;

    float acc[4][8][4];
    #pragma unroll
    for (int a = 0; a < 4; a++)
        #pragma unroll
        for (int c = 0; c < 8; c++)
            #pragma unroll
            for (int e = 0; e < 4; e++) acc[a][c][e] = 0.f;

    auto produce = [&](int ch) {
        char* stg = sm + (ch % 3) * LG_STAGE;
        const uint32_t dA = smem_u32(stg) + tid * 32;
        const uint8_t* sA = atiles + (size_t)ch * 8192 + tid * 32;
        CP_ASYNC16(dA,      sA);
        CP_ASYNC16(dA + 16, sA + 16);
        const uint32_t dW = smem_u32(stg + 8192) + tid * 32;
        const uint8_t* s0 = w0tiles + (size_t)ch * 8192 + tid * 32;
        const uint8_t* s1 = w1tiles + (size_t)ch * 8192 + tid * 32;
        CP_ASYNC16(dW,           s0);
        CP_ASYNC16(dW + 16,      s0 + 16);
        CP_ASYNC16(dW + 8192,      s1);
        CP_ASYNC16(dW + 8192 + 16, s1 + 16);
        CP_COMMIT();
    };

    // warp's W source: tile = nq>>1, local nfp base = (nq&1)*4
    const int woff = (nq >> 1) * 8192;
    const int nfp0 = (nq & 1) * 4;

    auto consume = [&](int ch) {
        const char* stg = sm + (ch % 3) * LG_STAGE;
        const char* Ah = stg;
        const char* Wt = stg + 8192 + woff;
        #pragma unroll
        for (int s = 0; s < 2; s++) {
            uint32_t a[4][4];
            #pragma unroll
            for (int mtc = 0; mtc < 4; mtc++) {
                uint4 v4 = *(const uint4*)(Ah + ((size_t)((s * 8 + mh * 4 + mtc) * 32 + lane)) * 16);
                a[mtc][0] = v4.x; a[mtc][1] = v4.y; a[mtc][2] = v4.z; a[mtc][3] = v4.w;
            }
            uint32_t b[8][2];
            #pragma unroll
            for (int p = 0; p < 4; p++) {
                uint4 u = *(const uint4*)(Wt + ((size_t)((s * 8 + nfp0 + p) * 32 + lane)) * 16);
                b[p*2+0][0] = u.x; b[p*2+0][1] = u.y;
                b[p*2+1][0] = u.z; b[p*2+1][1] = u.w;
            }
            #pragma unroll
            for (int mtc = 0; mtc < 4; mtc++)
                #pragma unroll
                for (int nf = 0; nf < 8; nf++)
                    MMA_F16(acc[mtc][nf], a[mtc], b[nf]);
        }
    };

    produce(0); produce(1);
    for (int ch = 0; ch < NCHUNK; ch++) {
        if (ch == NCHUNK - 1) { CP_WAIT0(); } else { CP_WAIT1(); }
        __syncthreads();
        if (ch + 2 < NCHUNK) produce(ch + 2);
        consume(ch);
    }

    // epilogue: warp covers 64 cols at nt2*256 + (nq>>1)*128 + (nq&1)*64
    const size_t rowbase = (size_t)bi * 128;
    const int colbase = nt2 * 256 + (nq >> 1) * 128 + (nq & 1) * 64 + (lane & 3) * 2;
    #pragma unroll
    for (int mtc = 0; mtc < 4; mtc++) {
        const int j0 = mh * 64 + mtc * 16 + (lane >> 2);
        #pragma unroll
        for (int nf = 0; nf < 8; nf++) {
            const int col = colbase + nf * 8;
            float* p0 = out + OFF_LOGITS + (rowbase + j0) * (size_t)VV + col;
            float* p1 = out + OFF_LOGITS + (rowbase + j0 + 8) * (size_t)VV + col;
            *(float2*)p0 = make_float2(acc[mtc][nf][0], acc[mtc][nf][1]);
            *(float2*)p1 = make_float2(acc[mtc][nf][2], acc[mtc][nf][3]);
        }
    }
}

// ---------------------------------------------------------------------------
// Mask kernels
// ---------------------------------------------------------------------------
__global__ void span_kernel(const int* __restrict__ mask_idx, float* __restrict__ out)
{
    const int b = blockIdx.x;
    const int t = threadIdx.x;
    __shared__ int mi[Msz];
    if (t < Msz) mi[t] = mask_idx[b * Msz + t];
    __syncthreads();
    int in = 0;
    #pragma unroll 8
    for (int m = 0; m < Msz; m++) in |= (mi[m] == t);
    g_span[b * Lsz + t] = in;
    out[OFF_MASKAA + (size_t)b * Lsz + t] = (float)in;
}

__global__ void diag_kernel(float* __restrict__ out)
{
    const int t = blockIdx.x * 256 + threadIdx.x;
    const int r = t & (Msz * Msz - 1);
    const int i = r >> 7, j = r & 127;
    out[OFF_DIAG + t] = (i == j) ? 1.0f : 0.0f;
}

__global__ void pair_kernel(float* __restrict__ out)
{
    const int idx = blockIdx.x * 256 + threadIdx.x;
    const int b   = idx >> 18;
    const int rem = idx & 262143;
    const int l1  = rem >> 8;
    const int l2g = (rem & 255) * 4;
    const float s1 = (float)g_span[b * Lsz + l1];
    const int* sp = g_span + b * Lsz + l2g;
    float4 o;
    o.x = s1 * sp[0]; o.y = s1 * sp[1]; o.z = s1 * sp[2]; o.w = s1 * sp[3];
    ((float4*)(out + OFF_PAIR))[idx] = o;
}

// ---------------------------------------------------------------------------
// Launch
// ---------------------------------------------------------------------------
extern "C" void kernel_launch(void* const* d_in, const int* in_sizes, int n_in,
                              void* d_out, int out_size)
{
    const float* x_enc    = (const float*)d_in[0];
    const float* ln_gamma = (const float*)d_in[1];
    const float* ln_beta  = (const float*)d_in[2];
    const float* Wq       = (const float*)d_in[3];
    const float* Wk       = (const float*)d_in[4];
    const float* W_embed  = (const float*)d_in[5];
    const float* W_mlm    = (const float*)d_in[6];
    const int*   mask_idx = (const int*)d_in[7];
    float* out = (float*)d_out;

    cudaFuncSetAttribute(qk_mma_kernel,
                         cudaFuncAttributeMaxDynamicSharedMemorySize, QK_SMEM);
    cudaFuncSetAttribute(logits_mma_kernel,
                         cudaFuncAttributeMaxDynamicSharedMemorySize, LG_SMEM);

    wsplit_kernel<<<dim3(NCHUNK, 8), 256>>>(W_embed);
    wqksplit_kernel<<<dim3(NCHUNK, 8, 2), 256>>>(Wq, Wk);
    ln_mlm_kernel<<<Bsz * Lsz, 256>>>(x_enc, ln_gamma, ln_beta, W_mlm, out);
    gather_kernel<<<Bsz * Msz, 256>>>(mask_idx);
    xmsplit_kernel<<<8, 256>>>();
    qk_mma_kernel<<<dim3(8, 8, 2), 256, QK_SMEM>>>();
    asplit_kernel<<<1024, 256>>>();
    logits_mma_kernel<<<dim3(4, Bsz * Msz), 256, LG_SMEM>>>(out);
    span_kernel<<<Bsz, Lsz>>>(mask_idx, out);
    diag_kernel<<<(Bsz * Msz * Msz) / 256, 256>>>(out);
    pair_kernel<<<(Bsz * Lsz * Lsz / 4) / 256, 256>>>(out);
}